// round 8
// baseline (speedup 1.0000x reference)
#include <cuda_runtime.h>
#include <math.h>

#define B_ 4
#define L_ 8192
#define D_ 2048
#define H_ 32
#define HD_ 64
#define CHUNK_ 256
#define NT_ 512

typedef unsigned long long ull;

__device__ float g_denoms[B_ * L_ * H_];
__device__ unsigned int g_cnt[B_ * (L_ / CHUNK_)];

// ---- packed f32x2 helpers (FFMA2: PTX-only, ptxas won't auto-fuse) ----
__device__ __forceinline__ ull pk2(float x, float y) {
    ull r; asm("mov.b64 %0,{%1,%2};" : "=l"(r) : "f"(x), "f"(y)); return r;
}
__device__ __forceinline__ void up2(ull v, float& x, float& y) {
    asm("mov.b64 {%0,%1},%2;" : "=f"(x), "=f"(y) : "l"(v));
}
__device__ __forceinline__ ull f2_(ull a, ull b, ull c) {
    ull d; asm("fma.rn.f32x2 %0,%1,%2,%3;" : "=l"(d) : "l"(a), "l"(b), "l"(c)); return d;
}
__device__ __forceinline__ ull m2_(ull a, ull b) {
    ull d; asm("mul.rn.f32x2 %0,%1,%2;" : "=l"(d) : "l"(a), "l"(b)); return d;
}
__device__ __forceinline__ ull a2_(ull a, ull b) {
    ull d; asm("add.rn.f32x2 %0,%1,%2;" : "=l"(d) : "l"(a), "l"(b)); return d;
}

__device__ __forceinline__ float red8(float v) {      // all-reduce over 8 ds-lanes
    v += __shfl_xor_sync(0xffffffffu, v, 1);
    v += __shfl_xor_sync(0xffffffffu, v, 2);
    v += __shfl_xor_sync(0xffffffffu, v, 4);
    return v;
}

// key slice: 4 packed pairs = 8 floats (dims 4*ds..4*ds+3 and 32+4*ds..)
__device__ __forceinline__ void ldk(ull* k, const float4* __restrict__ tile,
                                    int tok, int ds) {
    const ulonglong2 va = *reinterpret_cast<const ulonglong2*>(tile + tok * 16 + ds);
    const ulonglong2 vb = *reinterpret_cast<const ulonglong2*>(tile + tok * 16 + ds + 8);
    k[0] = va.x; k[1] = va.y; k[2] = vb.x; k[3] = vb.y;
}

// full dot(q_scaled, k) across warp (q pre-scaled by 1/8)
__device__ __forceinline__ float sc8(const ull* k, const ull* q) {
    const ull t = f2_(k[1], q[1], m2_(k[0], q[0]));
    const ull u = f2_(k[3], q[3], m2_(k[2], q[2]));
    float x, y; up2(a2_(t, u), x, y);
    return red8(x + y);
}

__device__ __forceinline__ void pv(ull* acc, ull p2, const ull* k) {
    acc[0] = f2_(p2, k[0], acc[0]); acc[1] = f2_(p2, k[1], acc[1]);
    acc[2] = f2_(p2, k[2], acc[2]); acc[3] = f2_(p2, k[3], acc[3]);
}

__device__ __forceinline__ void load_tile(const float* __restrict__ xh,
                                          int base_tok, float4* __restrict__ tile,
                                          int tid) {
    #pragma unroll
    for (int it = 0; it < 8; it++) {
        const int idx = tid + it * NT_;
        const int tok = idx >> 4;
        const int c   = idx & 15;
        tile[tok * 16 + c] = *reinterpret_cast<const float4*>(
            xh + (size_t)(base_tok + tok) * D_ + 4 * c);
    }
}

// Generic shared-key pass: 2 queries consume CNT keys at stride STRIDE from
// kbase, keys loaded once, NO max subtraction (scores are bounded; l >= 1).
template<int STRIDE, int CNT, int BLK>
__device__ __forceinline__ void rate_g(const float4* __restrict__ tile,
                                       int kbase, int ds,
                                       const ull* q0, const ull* q1,
                                       ull* t0, ull* t1, float& l0, float& l1) {
    #pragma unroll
    for (int blk = 0; blk < CNT / BLK; blk++) {
        ull K[BLK][4];
        float s0[BLK], s1[BLK];
        #pragma unroll
        for (int j = 0; j < BLK; j++) {
            ldk(K[j], tile, kbase + STRIDE * (blk * BLK + j), ds);
            s0[j] = sc8(K[j], q0);
            s1[j] = sc8(K[j], q1);
        }
        #pragma unroll
        for (int j = 0; j < BLK; j++) {
            const float e0 = __expf(s0[j]);
            const float e1 = __expf(s1[j]);
            l0 += e0; l1 += e1;
            pv(t0, pk2(e0, e0), K[j]);
            pv(t1, pk2(e1, e1), K[j]);
        }
    }
}

__device__ __forceinline__ void fold(ull* f, const ull* t, float l, float& den) {
    den += l;
    const float inv = 1.f / l;
    const ull iv = pk2(inv, inv);
    f[0] = f2_(iv, t[0], f[0]); f[1] = f2_(iv, t[1], f[1]);
    f[2] = f2_(iv, t[2], f[2]); f[3] = f2_(iv, t[3], f[3]);
}

// Private small rate (M=2/4): all keys cached, normalize directly into facc.
template<int M>
__device__ __forceinline__ void rate_small(const float4* __restrict__ tile,
                                           const ull* q, ull* facc, float& den,
                                           int t, int ds) {
    const int kb = (t & ~(M * M - 1)) + (t & (M - 1));
    ull K[M][4];
    float e[M];
    float sum = 0.f;
    #pragma unroll
    for (int j = 0; j < M; j++) {
        ldk(K[j], tile, kb + M * j, ds);
        e[j] = __expf(sc8(K[j], q));
        sum += e[j];
    }
    den += sum;
    const float inv = 1.f / sum;
    #pragma unroll
    for (int j = 0; j < M; j++) {
        const float p = e[j] * inv;
        pv(facc, pk2(p, p), K[j]);
    }
}

__global__ __launch_bounds__(NT_, 1)
void dda_fused_kernel(const float* __restrict__ x, float* __restrict__ out) {
    const int chunk = blockIdx.x;
    const int h     = blockIdx.y;
    const int b     = blockIdx.z;
    const int tid   = threadIdx.x;
    const int w     = tid >> 5;
    const int lane  = tid & 31;
    const int qs    = lane >> 3;
    const int ds    = lane & 7;

    extern __shared__ float4 tile[];          // 256*16 float4 = 65536 B

    const float* xh = x + (size_t)b * L_ * D_ + h * HD_;

    // queries, pre-scaled by 1/8 and packed: qq[qd][4]
    int t_loc[4];
    ull qq[4][4];
    const ull KQ = pk2(0.125f, 0.125f);
    #pragma unroll
    for (int qd = 0; qd < 4; qd++) {
        t_loc[qd] = (w + 16 * (qd >> 1)) + 32 * (4 * (qd & 1) + qs);
        const float* qp = xh + (size_t)(chunk * CHUNK_ + t_loc[qd]) * D_ + 4 * ds;
        const ulonglong2 va = *reinterpret_cast<const ulonglong2*>(qp);
        const ulonglong2 vb = *reinterpret_cast<const ulonglong2*>(qp + 32);
        qq[qd][0] = m2_(va.x, KQ); qq[qd][1] = m2_(va.y, KQ);
        qq[qd][2] = m2_(vb.x, KQ); qq[qd][3] = m2_(vb.y, KQ);
    }

    // ---- rate 5 (m=32): plain exp-sum accumulation over the 4 chunks of the
    // 1024-window; own chunk LAST so the tile stays resident for rates 4..0.
    ull  acc5[4][4] = {};                     // packed zeros
    float l5[4] = {0.f, 0.f, 0.f, 0.f};
    const int wch0 = chunk & ~3;
    const int myc  = chunk & 3;
    for (int cc = 1; cc <= 4; cc++) {
        const int c = wch0 + ((myc + cc) & 3);
        __syncthreads();
        load_tile(xh, c * CHUNK_, tile, tid);
        __syncthreads();
        #pragma unroll
        for (int rp = 0; rp < 2; rp++) {
            const int rr  = w + 16 * rp;      // key residue mod 32
            const int qd0 = 2 * rp, qd1 = 2 * rp + 1;
            rate_g<32, 8, 4>(tile, rr, ds, qq[qd0], qq[qd1],
                             acc5[qd0], acc5[qd1], l5[qd0], l5[qd1]);
        }
    }

    ull  facc[4][4] = {};
    float den[4] = {0.f, 0.f, 0.f, 0.f};
    #pragma unroll
    for (int qd = 0; qd < 4; qd++)
        fold(facc[qd], acc5[qd], l5[qd], den[qd]);

    // ---- rate M=16: all 4 queries share keys (tok = w + 16j); pair-sequential
    #pragma unroll
    for (int pr = 0; pr < 2; pr++) {
        const int qdA = pr, qdB = pr + 2;
        ull t0[4] = {}, t1[4] = {};
        float l0 = 0.f, l1 = 0.f;
        rate_g<16, 16, 4>(tile, w, ds, qq[qdA], qq[qdB], t0, t1, l0, l1);
        fold(facc[qdA], t0, l0, den[qdA]);
        fold(facc[qdB], t1, l1, den[qdB]);
    }

    // ---- rate M=8: pairs (0,2),(1,3) share the same 64-window + offset
    #pragma unroll
    for (int pr = 0; pr < 2; pr++) {
        const int qdA = pr, qdB = pr + 2;
        const int t = t_loc[qdA];
        const int kb8 = (t & ~63) + (t & 7);
        ull t0[4] = {}, t1[4] = {};
        float l0 = 0.f, l1 = 0.f;
        rate_g<8, 8, 4>(tile, kb8, ds, qq[qdA], qq[qdB], t0, t1, l0, l1);
        fold(facc[qdA], t0, l0, den[qdA]);
        fold(facc[qdB], t1, l1, den[qdB]);
    }

    // ---- rates M=4, M=2: private, fully cached, direct normalized accumulate
    #pragma unroll
    for (int qd = 0; qd < 4; qd++)
        rate_small<4>(tile, qq[qd], facc[qd], den[qd], t_loc[qd], ds);
    #pragma unroll
    for (int qd = 0; qd < 4; qd++)
        rate_small<2>(tile, qq[qd], facc[qd], den[qd], t_loc[qd], ds);

    // ---- rate 0: self key, prob = 1. q_scaled dot q_scaled = score/8.
    const ull E8 = pk2(8.f, 8.f);
    #pragma unroll
    for (int qd = 0; qd < 4; qd++) {
        const ull t = a2_(m2_(qq[qd][0], qq[qd][0]), m2_(qq[qd][1], qq[qd][1]));
        const ull u = a2_(m2_(qq[qd][2], qq[qd][2]), m2_(qq[qd][3], qq[qd][3]));
        float xx, yy; up2(a2_(t, u), xx, yy);
        den[qd] += __expf(red8(xx + yy) * 8.f);
        // out += q (unscaled) = 8 * q_scaled
        facc[qd][0] = f2_(E8, qq[qd][0], facc[qd][0]);
        facc[qd][1] = f2_(E8, qq[qd][1], facc[qd][1]);
        facc[qd][2] = f2_(E8, qq[qd][2], facc[qd][2]);
        facc[qd][3] = f2_(E8, qq[qd][3], facc[qd][3]);
    }

    // ---- writes
    #pragma unroll
    for (int qd = 0; qd < 4; qd++) {
        const int tg = chunk * CHUNK_ + t_loc[qd];
        if (ds == 0)
            g_denoms[((size_t)b * L_ + tg) * H_ + h] = den[qd];
        float* op = out + (size_t)b * L_ * D_ + (size_t)tg * D_ + h * HD_ + 4 * ds;
        float4 v0, v1;
        up2(facc[qd][0], v0.x, v0.y); up2(facc[qd][1], v0.z, v0.w);
        up2(facc[qd][2], v1.x, v1.y); up2(facc[qd][3], v1.z, v1.w);
        *reinterpret_cast<float4*>(op)      = v0;
        *reinterpret_cast<float4*>(op + 32) = v1;
    }

    // ---- last CTA per (b,chunk): head-softmax combine
    __threadfence();
    __shared__ unsigned int s_last;
    __syncthreads();
    if (tid == 0)
        s_last = (atomicInc(&g_cnt[b * (L_ / CHUNK_) + chunk], H_ - 1) == H_ - 1);
    __syncthreads();
    if (s_last) {
        const int k = lane;
        for (int t0 = w; t0 < CHUNK_; t0 += 16) {
            const size_t tok = (size_t)b * L_ + chunk * CHUNK_ + t0;
            const float v = __ldcg(&g_denoms[tok * H_ + k]);
            float mx = v;
            #pragma unroll
            for (int off = 16; off > 0; off >>= 1)
                mx = fmaxf(mx, __shfl_xor_sync(0xffffffffu, mx, off));
            const float e = __expf(v - mx);
            float sum = e;
            #pragma unroll
            for (int off = 16; off > 0; off >>= 1)
                sum += __shfl_xor_sync(0xffffffffu, sum, off);
            const float wgt = e / sum;
            float4* row = reinterpret_cast<float4*>(out + tok * D_);
            #pragma unroll
            for (int it = 0; it < 16; it++) {
                const int idx = k + 32 * it;
                const float ww = __shfl_sync(0xffffffffu, wgt, idx >> 4);
                float4 vv = __ldcg(&row[idx]);
                vv.x *= ww; vv.y *= ww; vv.z *= ww; vv.w *= ww;
                row[idx] = vv;
            }
        }
    }
}

extern "C" void kernel_launch(void* const* d_in, const int* in_sizes, int n_in,
                              void* d_out, int out_size) {
    const float* x = (const float*)d_in[0];
    float* out = (float*)d_out;

    const int smem_bytes = CHUNK_ * 16 * (int)sizeof(float4);   // 65536 B
    cudaFuncSetAttribute(dda_fused_kernel,
                         cudaFuncAttributeMaxDynamicSharedMemorySize, smem_bytes);

    dim3 grid(L_ / CHUNK_, H_, B_);
    dda_fused_kernel<<<grid, NT_, smem_bytes>>>(x, out);
}

// round 9
// speedup vs baseline: 1.2323x; 1.2323x over previous
#include <cuda_runtime.h>
#include <math.h>

#define B_ 4
#define L_ 8192
#define D_ 2048
#define H_ 32
#define HD_ 64
#define CHUNK_ 256
#define NT_ 512

__device__ float g_denoms[B_ * L_ * H_];
__device__ unsigned int g_cnt[B_ * (L_ / CHUNK_)];

struct K8 { float4 a, b; };

__device__ __forceinline__ K8 ldk(const float4* __restrict__ tile, int tok, int ds) {
    K8 k;
    k.a = tile[tok * 16 + ds];
    k.b = tile[tok * 16 + ds + 8];
    return k;
}
__device__ __forceinline__ float dotp(K8 k, const float* __restrict__ q) {
    float a0 = k.a.x * q[0], a1 = k.a.y * q[1], a2 = k.a.z * q[2], a3 = k.a.w * q[3];
    a0 = fmaf(k.b.x, q[4], a0); a1 = fmaf(k.b.y, q[5], a1);
    a2 = fmaf(k.b.z, q[6], a2); a3 = fmaf(k.b.w, q[7], a3);
    return (a0 + a1) + (a2 + a3);
}
__device__ __forceinline__ float red8(float v) {   // all-reduce over 8 ds-lanes
    v += __shfl_xor_sync(0xffffffffu, v, 1);
    v += __shfl_xor_sync(0xffffffffu, v, 2);
    v += __shfl_xor_sync(0xffffffffu, v, 4);
    return v;
}
__device__ __forceinline__ void pv8(float* __restrict__ a, float p, K8 k) {
    a[0] = fmaf(p, k.a.x, a[0]); a[1] = fmaf(p, k.a.y, a[1]);
    a[2] = fmaf(p, k.a.z, a[2]); a[3] = fmaf(p, k.a.w, a[3]);
    a[4] = fmaf(p, k.b.x, a[4]); a[5] = fmaf(p, k.b.y, a[5]);
    a[6] = fmaf(p, k.b.z, a[6]); a[7] = fmaf(p, k.b.w, a[7]);
}
__device__ __forceinline__ void fold(float* __restrict__ f, const float* __restrict__ t,
                                     float l, float& den) {
    den += l;
    const float inv = 1.f / l;
    #pragma unroll
    for (int i = 0; i < 8; i++) f[i] = fmaf(inv, t[i], f[i]);
}

__device__ __forceinline__ void load_tile(const float* __restrict__ xh,
                                          int base_tok, float4* __restrict__ tile,
                                          int tid) {
    #pragma unroll
    for (int it = 0; it < 8; it++) {
        const int idx = tid + it * NT_;
        const int tok = idx >> 4;
        const int c   = idx & 15;
        tile[tok * 16 + c] = *reinterpret_cast<const float4*>(
            xh + (size_t)(base_tok + tok) * D_ + 4 * c);
    }
}

// Two queries share the same CNT keys (stride STRIDE from kbase); keys loaded
// once; NO max subtraction (scores bounded, every group contains its self key
// so l >= 1). 4 independent score chains in flight per block.
template<int STRIDE, int CNT>
__device__ __forceinline__ void rate_pair(const float4* __restrict__ tile,
                                          int kbase, int ds,
                                          const float* qA, const float* qB,
                                          float* tA, float* tB,
                                          float& lA, float& lB) {
    #pragma unroll
    for (int blk = 0; blk < CNT / 2; blk++) {
        const K8 k0 = ldk(tile, kbase + STRIDE * (2 * blk + 0), ds);
        const K8 k1 = ldk(tile, kbase + STRIDE * (2 * blk + 1), ds);
        const float sA0 = red8(dotp(k0, qA));
        const float sA1 = red8(dotp(k1, qA));
        const float sB0 = red8(dotp(k0, qB));
        const float sB1 = red8(dotp(k1, qB));
        const float eA0 = __expf(sA0), eA1 = __expf(sA1);
        const float eB0 = __expf(sB0), eB1 = __expf(sB1);
        lA += eA0 + eA1;
        lB += eB0 + eB1;
        pv8(tA, eA0, k0); pv8(tA, eA1, k1);
        pv8(tB, eB0, k0); pv8(tB, eB1, k1);
    }
}

// Two queries with PRIVATE key streams (M keys each, stride M): 2 chains/step.
template<int M>
__device__ __forceinline__ void rate_priv(const float4* __restrict__ tile,
                                          int kbA, int kbB, int ds,
                                          const float* qA, const float* qB,
                                          float* tA, float* tB,
                                          float& lA, float& lB) {
    #pragma unroll
    for (int j = 0; j < M; j++) {
        const K8 kA = ldk(tile, kbA + M * j, ds);
        const K8 kB = ldk(tile, kbB + M * j, ds);
        const float eA = __expf(red8(dotp(kA, qA)));
        const float eB = __expf(red8(dotp(kB, qB)));
        lA += eA; lB += eB;
        pv8(tA, eA, kA);
        pv8(tB, eB, kB);
    }
}

__global__ __launch_bounds__(NT_, 1)
void dda_fused_kernel(const float* __restrict__ x, float* __restrict__ out) {
    const int chunk = blockIdx.x;
    const int h     = blockIdx.y;
    const int b     = blockIdx.z;
    const int tid   = threadIdx.x;
    const int w     = tid >> 5;
    const int lane  = tid & 31;
    const int qs    = lane >> 3;
    const int ds    = lane & 7;

    extern __shared__ float4 tile[];          // 256*16 float4 = 65536 B

    const float* xh = x + (size_t)b * L_ * D_ + h * HD_;

    // queries pre-scaled by 1/8 (score = red8(dot(q_scaled, k)))
    int   t_loc[4];
    float q[4][8];
    #pragma unroll
    for (int qd = 0; qd < 4; qd++) {
        t_loc[qd] = (w + 16 * (qd >> 1)) + 32 * (4 * (qd & 1) + qs);
        const float* qp = xh + (size_t)(chunk * CHUNK_ + t_loc[qd]) * D_ + 4 * ds;
        const float4 va = *reinterpret_cast<const float4*>(qp);
        const float4 vb = *reinterpret_cast<const float4*>(qp + 32);
        q[qd][0] = va.x * 0.125f; q[qd][1] = va.y * 0.125f;
        q[qd][2] = va.z * 0.125f; q[qd][3] = va.w * 0.125f;
        q[qd][4] = vb.x * 0.125f; q[qd][5] = vb.y * 0.125f;
        q[qd][6] = vb.z * 0.125f; q[qd][7] = vb.w * 0.125f;
    }

    // ---- rate 5 (m=32): order-free exp-sum over the 4 chunks of the 1024-
    // window (no max, no rescale); own chunk LAST so tile stays resident.
    float acc5[4][8] = {};
    float l5[4] = {0.f, 0.f, 0.f, 0.f};
    const int wch0 = chunk & ~3;
    const int myc  = chunk & 3;
    for (int cc = 1; cc <= 4; cc++) {
        const int c = wch0 + ((myc + cc) & 3);
        __syncthreads();
        load_tile(xh, c * CHUNK_, tile, tid);
        __syncthreads();
        rate_pair<32, 8>(tile, w, ds, q[0], q[1], acc5[0], acc5[1], l5[0], l5[1]);
        rate_pair<32, 8>(tile, w + 16, ds, q[2], q[3], acc5[2], acc5[3], l5[2], l5[3]);
    }

    // finalize rate 5 in place: facc = acc5 / l5, den = l5
    float den[4];
    #pragma unroll
    for (int qd = 0; qd < 4; qd++) {
        den[qd] = l5[qd];
        const float inv = 1.f / l5[qd];
        #pragma unroll
        for (int i = 0; i < 8; i++) acc5[qd][i] *= inv;
    }
    #define facc acc5

    // ---- rate M=16: keys tok = w + 16j shared by all 4 queries
    {
        float t0[8] = {}, t1[8] = {};
        float l0 = 0.f, l1 = 0.f;
        rate_pair<16, 16>(tile, w, ds, q[0], q[1], t0, t1, l0, l1);
        fold(facc[0], t0, l0, den[0]);
        fold(facc[1], t1, l1, den[1]);
        #pragma unroll
        for (int i = 0; i < 8; i++) { t0[i] = 0.f; t1[i] = 0.f; }
        l0 = 0.f; l1 = 0.f;
        rate_pair<16, 16>(tile, w, ds, q[2], q[3], t0, t1, l0, l1);
        fold(facc[2], t0, l0, den[2]);
        fold(facc[3], t1, l1, den[3]);
    }

    // ---- rate M=8: pairs (0,2),(1,3) share the same 64-window + offset
    #pragma unroll
    for (int pr = 0; pr < 2; pr++) {
        const int qdA = pr, qdB = pr + 2;
        const int t = t_loc[qdA];
        const int kb8 = (t & ~63) + (t & 7);
        float t0[8] = {}, t1[8] = {};
        float l0 = 0.f, l1 = 0.f;
        rate_pair<8, 8>(tile, kb8, ds, q[qdA], q[qdB], t0, t1, l0, l1);
        fold(facc[qdA], t0, l0, den[qdA]);
        fold(facc[qdB], t1, l1, den[qdB]);
    }

    // ---- rates M=4, M=2: private key streams, interleaved in pairs
    #pragma unroll
    for (int pr = 0; pr < 2; pr++) {
        const int qdA = pr, qdB = pr + 2;
        const int tA = t_loc[qdA], tB = t_loc[qdB];
        float t0[8] = {}, t1[8] = {};
        float l0 = 0.f, l1 = 0.f;
        rate_priv<4>(tile, (tA & ~15) + (tA & 3), (tB & ~15) + (tB & 3), ds,
                     q[qdA], q[qdB], t0, t1, l0, l1);
        fold(facc[qdA], t0, l0, den[qdA]);
        fold(facc[qdB], t1, l1, den[qdB]);
        #pragma unroll
        for (int i = 0; i < 8; i++) { t0[i] = 0.f; t1[i] = 0.f; }
        l0 = 0.f; l1 = 0.f;
        rate_priv<2>(tile, (tA & ~3) + (tA & 1), (tB & ~3) + (tB & 1), ds,
                     q[qdA], q[qdB], t0, t1, l0, l1);
        fold(facc[qdA], t0, l0, den[qdA]);
        fold(facc[qdB], t1, l1, den[qdB]);
    }

    // ---- rate 0: self key, prob = 1; self score = 8 * |q_scaled|^2
    #pragma unroll
    for (int qd = 0; qd < 4; qd++) {
        float s = 0.f;
        #pragma unroll
        for (int i = 0; i < 8; i++) s = fmaf(q[qd][i], q[qd][i], s);
        den[qd] += __expf(red8(s) * 8.f);
        #pragma unroll
        for (int i = 0; i < 8; i++) facc[qd][i] = fmaf(8.f, q[qd][i], facc[qd][i]);
    }

    // ---- writes
    #pragma unroll
    for (int qd = 0; qd < 4; qd++) {
        const int tg = chunk * CHUNK_ + t_loc[qd];
        if (ds == 0)
            g_denoms[((size_t)b * L_ + tg) * H_ + h] = den[qd];
        float* op = out + (size_t)b * L_ * D_ + (size_t)tg * D_ + h * HD_ + 4 * ds;
        *reinterpret_cast<float4*>(op) =
            make_float4(facc[qd][0], facc[qd][1], facc[qd][2], facc[qd][3]);
        *reinterpret_cast<float4*>(op + 32) =
            make_float4(facc[qd][4], facc[qd][5], facc[qd][6], facc[qd][7]);
    }
    #undef facc

    // ---- last CTA per (b,chunk): head-softmax combine
    __threadfence();
    __shared__ unsigned int s_last;
    __syncthreads();
    if (tid == 0)
        s_last = (atomicInc(&g_cnt[b * (L_ / CHUNK_) + chunk], H_ - 1) == H_ - 1);
    __syncthreads();
    if (s_last) {
        const int k = lane;
        for (int t0 = w; t0 < CHUNK_; t0 += 16) {
            const size_t tok = (size_t)b * L_ + chunk * CHUNK_ + t0;
            const float v = __ldcg(&g_denoms[tok * H_ + k]);
            float mx = v;
            #pragma unroll
            for (int off = 16; off > 0; off >>= 1)
                mx = fmaxf(mx, __shfl_xor_sync(0xffffffffu, mx, off));
            const float e = __expf(v - mx);
            float sum = e;
            #pragma unroll
            for (int off = 16; off > 0; off >>= 1)
                sum += __shfl_xor_sync(0xffffffffu, sum, off);
            const float wgt = e / sum;
            float4* row = reinterpret_cast<float4*>(out + tok * D_);
            #pragma unroll
            for (int it = 0; it < 16; it++) {
                const int idx = k + 32 * it;
                const float ww = __shfl_sync(0xffffffffu, wgt, idx >> 4);
                float4 vv = __ldcg(&row[idx]);
                vv.x *= ww; vv.y *= ww; vv.z *= ww; vv.w *= ww;
                row[idx] = vv;
            }
        }
    }
}

extern "C" void kernel_launch(void* const* d_in, const int* in_sizes, int n_in,
                              void* d_out, int out_size) {
    const float* x = (const float*)d_in[0];
    float* out = (float*)d_out;

    const int smem_bytes = CHUNK_ * 16 * (int)sizeof(float4);   // 65536 B
    cudaFuncSetAttribute(dda_fused_kernel,
                         cudaFuncAttributeMaxDynamicSharedMemorySize, smem_bytes);

    dim3 grid(L_ / CHUNK_, H_, B_);
    dda_fused_kernel<<<grid, NT_, smem_bytes>>>(x, out);
}

// round 11
// speedup vs baseline: 1.2506x; 1.0148x over previous
#include <cuda_runtime.h>
#include <math.h>

#define B_ 4
#define L_ 8192
#define D_ 2048
#define H_ 32
#define HD_ 64
#define CHUNK_ 256
#define NT_ 512

#define QSCALE_ 0.1803368801111737f     /* 0.125 * log2(e) */
#define QUNDO_  5.545177444479562f      /* 1 / QSCALE_ / log2(e) * ... = 8/log2(e) */

__device__ float g_denoms[B_ * L_ * H_];
__device__ unsigned int g_cnt[B_ * (L_ / CHUNK_)];

// MUFU.EX2 directly (same unit __expf lowers to; input already in log2 domain)
__device__ __forceinline__ float ex2(float v) {
    float r; asm("ex2.approx.f32 %0, %1;" : "=f"(r) : "f"(v)); return r;
}

struct K8 { float4 a, b; };

__device__ __forceinline__ K8 ldk(const float4* __restrict__ tile, int tok, int ds) {
    K8 k;
    k.a = tile[tok * 16 + ds];
    k.b = tile[tok * 16 + ds + 8];
    return k;
}
__device__ __forceinline__ float dotp(K8 k, const float* __restrict__ q) {
    float a0 = k.a.x * q[0], a1 = k.a.y * q[1], a2 = k.a.z * q[2], a3 = k.a.w * q[3];
    a0 = fmaf(k.b.x, q[4], a0); a1 = fmaf(k.b.y, q[5], a1);
    a2 = fmaf(k.b.z, q[6], a2); a3 = fmaf(k.b.w, q[7], a3);
    return (a0 + a1) + (a2 + a3);
}
__device__ __forceinline__ float red8(float v) {   // all-reduce over 8 ds-lanes
    v += __shfl_xor_sync(0xffffffffu, v, 1);
    v += __shfl_xor_sync(0xffffffffu, v, 2);
    v += __shfl_xor_sync(0xffffffffu, v, 4);
    return v;
}
// Transpose-reduce 4 partials over the 8 lanes of an octet:
// returns exp2(full score of key (ds&3)) on every lane.
__device__ __forceinline__ float tred4(const float* __restrict__ p, int ds) {
    const bool b0 = (ds & 1), b1 = (ds & 2);
    const float s0 = b0 ? p[0] : p[1];
    const float s1 = b0 ? p[2] : p[3];
    const float k0 = b0 ? p[1] : p[0];
    const float k1 = b0 ? p[3] : p[2];
    const float v0 = k0 + __shfl_xor_sync(0xffffffffu, s0, 1);
    const float v1 = k1 + __shfl_xor_sync(0xffffffffu, s1, 1);
    const float s2 = b1 ? v0 : v1;
    const float k2 = b1 ? v1 : v0;
    const float v2 = k2 + __shfl_xor_sync(0xffffffffu, s2, 2);
    const float v3 = v2 + __shfl_xor_sync(0xffffffffu, v2, 4);
    return ex2(v3);
}
__device__ __forceinline__ void pv8(float* __restrict__ a, float p, K8 k) {
    a[0] = fmaf(p, k.a.x, a[0]); a[1] = fmaf(p, k.a.y, a[1]);
    a[2] = fmaf(p, k.a.z, a[2]); a[3] = fmaf(p, k.a.w, a[3]);
    a[4] = fmaf(p, k.b.x, a[4]); a[5] = fmaf(p, k.b.y, a[5]);
    a[6] = fmaf(p, k.b.z, a[6]); a[7] = fmaf(p, k.b.w, a[7]);
}
__device__ __forceinline__ void fold(float* __restrict__ f, const float* __restrict__ t,
                                     float l, float& den) {
    den += l;
    const float inv = 1.f / l;
    #pragma unroll
    for (int i = 0; i < 8; i++) f[i] = fmaf(inv, t[i], f[i]);
}

__device__ __forceinline__ void load_tile(const float* __restrict__ xh,
                                          int base_tok, float4* __restrict__ tile,
                                          int tid) {
    #pragma unroll
    for (int it = 0; it < 8; it++) {
        const int idx = tid + it * NT_;
        const int tok = idx >> 4;
        const int c   = idx & 15;
        tile[tok * 16 + c] = *reinterpret_cast<const float4*>(
            xh + (size_t)(base_tok + tok) * D_ + 4 * c);
    }
}

// Two queries share CNT keys (stride STRIDE); 4-key blocks with transposed
// score reduction; ONE MUFU exp per key per query; keys loaded once.
// No max subtraction (scores bounded; every group contains its self key).
template<int STRIDE, int CNT>
__device__ __forceinline__ void rate_pair(const float4* __restrict__ tile,
                                          int kbase, int ds,
                                          const float* qA, const float* qB,
                                          float* tA, float* tB,
                                          float& lA, float& lB) {
    #pragma unroll
    for (int blk = 0; blk < CNT / 4; blk++) {
        K8 K[4];
        float pA[4], pB[4];
        #pragma unroll
        for (int j = 0; j < 4; j++) {
            K[j] = ldk(tile, kbase + STRIDE * (4 * blk + j), ds);
            pA[j] = dotp(K[j], qA);
            pB[j] = dotp(K[j], qB);
        }
        const float eA = tred4(pA, ds);      // exp2(score of key ds&3)
        const float eB = tred4(pB, ds);
        #pragma unroll
        for (int j = 0; j < 4; j++) {
            const float aj = __shfl_sync(0xffffffffu, eA, j, 8);
            const float bj = __shfl_sync(0xffffffffu, eB, j, 8);
            lA += aj; lB += bj;
            pv8(tA, aj, K[j]);
            pv8(tB, bj, K[j]);
        }
    }
}

// Two queries with PRIVATE key streams (M keys each, stride M).
template<int M>
__device__ __forceinline__ void rate_priv(const float4* __restrict__ tile,
                                          int kbA, int kbB, int ds,
                                          const float* qA, const float* qB,
                                          float* tA, float* tB,
                                          float& lA, float& lB) {
    #pragma unroll
    for (int j = 0; j < M; j++) {
        const K8 kA = ldk(tile, kbA + M * j, ds);
        const K8 kB = ldk(tile, kbB + M * j, ds);
        const float eA = ex2(red8(dotp(kA, qA)));
        const float eB = ex2(red8(dotp(kB, qB)));
        lA += eA; lB += eB;
        pv8(tA, eA, kA);
        pv8(tB, eB, kB);
    }
}

__global__ __launch_bounds__(NT_, 1)
void dda_fused_kernel(const float* __restrict__ x, float* __restrict__ out) {
    const int chunk = blockIdx.x;
    const int h     = blockIdx.y;
    const int b     = blockIdx.z;
    const int tid   = threadIdx.x;
    const int w     = tid >> 5;
    const int lane  = tid & 31;
    const int qs    = lane >> 3;
    const int ds    = lane & 7;

    extern __shared__ float4 tile[];          // 256*16 float4 = 65536 B

    const float* xh = x + (size_t)b * L_ * D_ + h * HD_;

    // queries pre-scaled by 0.125*log2(e): dot -> score in log2 domain
    int   t_loc[4];
    float q[4][8];
    #pragma unroll
    for (int qd = 0; qd < 4; qd++) {
        t_loc[qd] = (w + 16 * (qd >> 1)) + 32 * (4 * (qd & 1) + qs);
        const float* qp = xh + (size_t)(chunk * CHUNK_ + t_loc[qd]) * D_ + 4 * ds;
        const float4 va = *reinterpret_cast<const float4*>(qp);
        const float4 vb = *reinterpret_cast<const float4*>(qp + 32);
        q[qd][0] = va.x * QSCALE_; q[qd][1] = va.y * QSCALE_;
        q[qd][2] = va.z * QSCALE_; q[qd][3] = va.w * QSCALE_;
        q[qd][4] = vb.x * QSCALE_; q[qd][5] = vb.y * QSCALE_;
        q[qd][6] = vb.z * QSCALE_; q[qd][7] = vb.w * QSCALE_;
    }

    // ---- rate 5 (m=32): order-free exp-sum over the 4 chunks of the 1024-
    // window; own chunk LAST so the tile stays resident for rates 4..0.
    float acc5[4][8] = {};
    float l5[4] = {0.f, 0.f, 0.f, 0.f};
    const int wch0 = chunk & ~3;
    const int myc  = chunk & 3;
    for (int cc = 1; cc <= 4; cc++) {
        const int c = wch0 + ((myc + cc) & 3);
        __syncthreads();
        load_tile(xh, c * CHUNK_, tile, tid);
        __syncthreads();
        rate_pair<32, 8>(tile, w, ds, q[0], q[1], acc5[0], acc5[1], l5[0], l5[1]);
        rate_pair<32, 8>(tile, w + 16, ds, q[2], q[3], acc5[2], acc5[3], l5[2], l5[3]);
    }

    // finalize rate 5 in place: facc = acc5 / l5, den = l5
    float den[4];
    #pragma unroll
    for (int qd = 0; qd < 4; qd++) {
        den[qd] = l5[qd];
        const float inv = 1.f / l5[qd];
        #pragma unroll
        for (int i = 0; i < 8; i++) acc5[qd][i] *= inv;
    }
    #define facc acc5

    // ---- rate M=16: keys tok = w + 16j shared by all 4 queries
    {
        float t0[8] = {}, t1[8] = {};
        float l0 = 0.f, l1 = 0.f;
        rate_pair<16, 16>(tile, w, ds, q[0], q[1], t0, t1, l0, l1);
        fold(facc[0], t0, l0, den[0]);
        fold(facc[1], t1, l1, den[1]);
        #pragma unroll
        for (int i = 0; i < 8; i++) { t0[i] = 0.f; t1[i] = 0.f; }
        l0 = 0.f; l1 = 0.f;
        rate_pair<16, 16>(tile, w, ds, q[2], q[3], t0, t1, l0, l1);
        fold(facc[2], t0, l0, den[2]);
        fold(facc[3], t1, l1, den[3]);
    }

    // ---- rate M=8: pairs (0,2),(1,3) share the same 64-window + offset
    #pragma unroll
    for (int pr = 0; pr < 2; pr++) {
        const int qdA = pr, qdB = pr + 2;
        const int t = t_loc[qdA];
        const int kb8 = (t & ~63) + (t & 7);
        float t0[8] = {}, t1[8] = {};
        float l0 = 0.f, l1 = 0.f;
        rate_pair<8, 8>(tile, kb8, ds, q[qdA], q[qdB], t0, t1, l0, l1);
        fold(facc[qdA], t0, l0, den[qdA]);
        fold(facc[qdB], t1, l1, den[qdB]);
    }

    // ---- rates M=4, M=2: private key streams, interleaved in pairs
    #pragma unroll
    for (int pr = 0; pr < 2; pr++) {
        const int qdA = pr, qdB = pr + 2;
        const int tA = t_loc[qdA], tB = t_loc[qdB];
        float t0[8] = {}, t1[8] = {};
        float l0 = 0.f, l1 = 0.f;
        rate_priv<4>(tile, (tA & ~15) + (tA & 3), (tB & ~15) + (tB & 3), ds,
                     q[qdA], q[qdB], t0, t1, l0, l1);
        fold(facc[qdA], t0, l0, den[qdA]);
        fold(facc[qdB], t1, l1, den[qdB]);
        #pragma unroll
        for (int i = 0; i < 8; i++) { t0[i] = 0.f; t1[i] = 0.f; }
        l0 = 0.f; l1 = 0.f;
        rate_priv<2>(tile, (tA & ~3) + (tA & 1), (tB & ~3) + (tB & 1), ds,
                     q[qdA], q[qdB], t0, t1, l0, l1);
        fold(facc[qdA], t0, l0, den[qdA]);
        fold(facc[qdB], t1, l1, den[qdB]);
    }

    // ---- rate 0: self key, prob = 1. red8(|q'|^2) * QUNDO_ = score*log2(e).
    #pragma unroll
    for (int qd = 0; qd < 4; qd++) {
        float s = 0.f;
        #pragma unroll
        for (int i = 0; i < 8; i++) s = fmaf(q[qd][i], q[qd][i], s);
        den[qd] += ex2(red8(s) * QUNDO_);
        #pragma unroll
        for (int i = 0; i < 8; i++)
            facc[qd][i] = fmaf(QUNDO_ * 0.6931471805599453f * 8.f / 8.f /*==1/QSCALE_*/,
                               0.f, facc[qd][i]);   // placeholder no-op (kept simple below)
    }
    // += q (unscaled) = q' / QSCALE_
    #pragma unroll
    for (int qd = 0; qd < 4; qd++) {
        const float invs = 1.f / QSCALE_;
        #pragma unroll
        for (int i = 0; i < 8; i++)
            facc[qd][i] = fmaf(invs, q[qd][i], facc[qd][i]);
    }

    // ---- writes
    #pragma unroll
    for (int qd = 0; qd < 4; qd++) {
        const int tg = chunk * CHUNK_ + t_loc[qd];
        if (ds == 0)
            g_denoms[((size_t)b * L_ + tg) * H_ + h] = den[qd];
        float* op = out + (size_t)b * L_ * D_ + (size_t)tg * D_ + h * HD_ + 4 * ds;
        *reinterpret_cast<float4*>(op) =
            make_float4(facc[qd][0], facc[qd][1], facc[qd][2], facc[qd][3]);
        *reinterpret_cast<float4*>(op + 32) =
            make_float4(facc[qd][4], facc[qd][5], facc[qd][6], facc[qd][7]);
    }
    #undef facc

    // ---- last CTA per (b,chunk): head-softmax combine
    __threadfence();
    __shared__ unsigned int s_last;
    __syncthreads();
    if (tid == 0)
        s_last = (atomicInc(&g_cnt[b * (L_ / CHUNK_) + chunk], H_ - 1) == H_ - 1);
    __syncthreads();
    if (s_last) {
        const int k = lane;
        for (int t0 = w; t0 < CHUNK_; t0 += 16) {
            const size_t tok = (size_t)b * L_ + chunk * CHUNK_ + t0;
            const float v = __ldcg(&g_denoms[tok * H_ + k]);
            float mx = v;
            #pragma unroll
            for (int off = 16; off > 0; off >>= 1)
                mx = fmaxf(mx, __shfl_xor_sync(0xffffffffu, mx, off));
            const float e = __expf(v - mx);
            float sum = e;
            #pragma unroll
            for (int off = 16; off > 0; off >>= 1)
                sum += __shfl_xor_sync(0xffffffffu, sum, off);
            const float wgt = e / sum;
            float4* row = reinterpret_cast<float4*>(out + tok * D_);
            #pragma unroll
            for (int it = 0; it < 16; it++) {
                const int idx = k + 32 * it;
                const float ww = __shfl_sync(0xffffffffu, wgt, idx >> 4);
                float4 vv = __ldcg(&row[idx]);
                vv.x *= ww; vv.y *= ww; vv.z *= ww; vv.w *= ww;
                row[idx] = vv;
            }
        }
    }
}

extern "C" void kernel_launch(void* const* d_in, const int* in_sizes, int n_in,
                              void* d_out, int out_size) {
    const float* x = (const float*)d_in[0];
    float* out = (float*)d_out;

    const int smem_bytes = CHUNK_ * 16 * (int)sizeof(float4);   // 65536 B
    cudaFuncSetAttribute(dda_fused_kernel,
                         cudaFuncAttributeMaxDynamicSharedMemorySize, smem_bytes);

    dim3 grid(L_ / CHUNK_, H_, B_);
    dda_fused_kernel<<<grid, NT_, smem_bytes>>>(x, out);
}

// round 12
// speedup vs baseline: 2.1084x; 1.6859x over previous
#include <cuda_runtime.h>
#include <math.h>

#define B_ 4
#define L_ 8192
#define D_ 2048
#define H_ 32
#define HD_ 64
#define CHUNK_ 256
#define NT_ 512

#define QSCALE_ 0.1803368801111737f     /* 0.125 * log2(e) */
#define QINV_   5.545177444479562f      /* 1 / QSCALE_ */

__device__ float g_denoms[B_ * L_ * H_];
__device__ unsigned int g_cnt[B_ * (L_ / CHUNK_)];

__device__ __forceinline__ float ex2(float v) {
    float r; asm("ex2.approx.f32 %0, %1;" : "=f"(r) : "f"(v)); return r;
}
// column swizzle within each 8-float4 half; decorrelates banks for toks that
// differ in bits 4..7 (the private-rate strides). Same tok -> same sw, so all
// broadcast patterns are unaffected.
__device__ __forceinline__ int swz(int tok) {
    return ((tok >> 4) ^ (tok >> 6)) & 7;
}

__device__ __forceinline__ void load_tile(const float* __restrict__ xh,
                                          int base_tok, float4* __restrict__ tile,
                                          int tid) {
    #pragma unroll
    for (int it = 0; it < 8; it++) {
        const int idx = tid + it * NT_;
        const int tok = idx >> 4;
        const int c   = idx & 15;
        tile[tok * 16 + (c & 8) + ((c & 7) ^ swz(tok))] =
            *reinterpret_cast<const float4*>(xh + (size_t)(base_tok + tok) * D_ + 4 * c);
    }
}

// exp2(score) for this thread's query vs key tok. Half-dot (32 dims) + ONE
// shfl to combine with the partner lane (lane^16); both lanes get e.
__device__ __forceinline__ float key_e(const float4* __restrict__ kp, int sw,
                                       const float4* __restrict__ q4) {
    float a0 = 0.f, a1 = 0.f, a2 = 0.f, a3 = 0.f;
    #pragma unroll
    for (int i = 0; i < 8; i++) {
        const float4 k = kp[i ^ sw];
        a0 = fmaf(k.x, q4[i].x, a0); a1 = fmaf(k.y, q4[i].y, a1);
        a2 = fmaf(k.z, q4[i].z, a2); a3 = fmaf(k.w, q4[i].w, a3);
    }
    float s = (a0 + a1) + (a2 + a3);
    s += __shfl_xor_sync(0xffffffffu, s, 16);
    return ex2(s);
}
// PV: reload key (broadcast LDS) and accumulate e * key into tmp.
__device__ __forceinline__ void key_pv(float4* __restrict__ acc,
                                       const float4* __restrict__ kp, int sw, float e) {
    #pragma unroll
    for (int i = 0; i < 8; i++) {
        const float4 k = kp[i ^ sw];
        acc[i].x = fmaf(e, k.x, acc[i].x); acc[i].y = fmaf(e, k.y, acc[i].y);
        acc[i].z = fmaf(e, k.z, acc[i].z); acc[i].w = fmaf(e, k.w, acc[i].w);
    }
}

// CNT keys at stride STRIDE from per-lane base kb; unnormalized exp-sum into
// (tmp, l). No max subtraction (scores bounded; every group has its self key).
template<int CNT, int STRIDE>
__device__ __forceinline__ void rate_run(const float4* __restrict__ tile, int kb,
                                         int hf8, const float4* __restrict__ q4,
                                         float4* __restrict__ tmp, float& l) {
    #pragma unroll
    for (int j = 0; j < CNT; j++) {
        const int tok = kb + STRIDE * j;
        const float4* kp = tile + tok * 16 + hf8;
        const int sw = swz(tok);
        const float e = key_e(kp, sw, q4);
        l += e;
        key_pv(tmp, kp, sw, e);
    }
}

__global__ __launch_bounds__(NT_, 1)
void dda_fused_kernel(const float* __restrict__ x, float* __restrict__ out) {
    const int chunk = blockIdx.x;             // 0..31
    const int h     = blockIdx.y;             // 0..31
    const int b     = blockIdx.z;             // 0..3
    const int tid   = threadIdx.x;
    const int w     = tid >> 5;               // warp 0..15
    const int lane  = tid & 31;
    const int qs    = lane & 15;              // query slot
    const int hf    = lane >> 4;              // dim half (0: dims 0..31)
    const int hf8   = hf * 8;

    extern __shared__ float4 tile[];          // 256*16 float4 = 65536 B

    const float* xh = x + (size_t)b * L_ * D_ + h * HD_;

    const int t_loc = w + 16 * qs;            // one query per thread (2 lanes/query)
    const int t_glob = chunk * CHUNK_ + t_loc;

    // my half of the query, pre-scaled by 0.125*log2(e)
    float4 q4[8];
    {
        const float* qp = xh + (size_t)t_glob * D_ + 32 * hf;
        #pragma unroll
        for (int i = 0; i < 8; i++) {
            float4 v = *reinterpret_cast<const float4*>(qp + 4 * i);
            v.x *= QSCALE_; v.y *= QSCALE_; v.z *= QSCALE_; v.w *= QSCALE_;
            q4[i] = v;
        }
    }

    float4 facc[8];
    #pragma unroll
    for (int i = 0; i < 8; i++) facc[i] = make_float4(0.f, 0.f, 0.f, 0.f);
    float den = 0.f;

    float4 tmp[8];
    float  l;

    // ---- rate 5 (m=32): unnormalized exp-sum over the 4 chunks of the
    // 1024-window; own chunk LAST so the tile stays resident for rates 4..0.
    // Key residue = t mod 32 = w + 16*(qs&1): one LDS serves 8 queries.
    {
        #pragma unroll
        for (int i = 0; i < 8; i++) tmp[i] = make_float4(0.f, 0.f, 0.f, 0.f);
        l = 0.f;
        const int rr   = w + 16 * (qs & 1);
        const int wch0 = chunk & ~3;
        const int myc  = chunk & 3;
        for (int cc = 1; cc <= 4; cc++) {
            const int c = wch0 + ((myc + cc) & 3);
            __syncthreads();
            load_tile(xh, c * CHUNK_, tile, tid);
            __syncthreads();
            rate_run<8, 32>(tile, rr, hf8, q4, tmp, l);
        }
        den += l;
        const float inv = 1.f / l;
        #pragma unroll
        for (int i = 0; i < 8; i++) {
            facc[i].x = fmaf(inv, tmp[i].x, facc[i].x);
            facc[i].y = fmaf(inv, tmp[i].y, facc[i].y);
            facc[i].z = fmaf(inv, tmp[i].z, facc[i].z);
            facc[i].w = fmaf(inv, tmp[i].w, facc[i].w);
        }
    }

    // ---- rates 4..1 on the resident own-chunk tile; temp reused per rate.
    #pragma unroll
    for (int r = 0; r < 4; r++) {
        #pragma unroll
        for (int i = 0; i < 8; i++) tmp[i] = make_float4(0.f, 0.f, 0.f, 0.f);
        l = 0.f;
        if (r == 0)      rate_run<16, 16>(tile, w, hf8, q4, tmp, l);                       // keys shared by 16 queries
        else if (r == 1) rate_run<8, 8>(tile, (t_loc & ~63) + (w & 7), hf8, q4, tmp, l);   // shared by 4
        else if (r == 2) rate_run<4, 4>(tile, (t_loc & ~15) + (w & 3), hf8, q4, tmp, l);   // private
        else             rate_run<2, 2>(tile, (t_loc & ~3) + (w & 1), hf8, q4, tmp, l);    // private
        den += l;
        const float inv = 1.f / l;
        #pragma unroll
        for (int i = 0; i < 8; i++) {
            facc[i].x = fmaf(inv, tmp[i].x, facc[i].x);
            facc[i].y = fmaf(inv, tmp[i].y, facc[i].y);
            facc[i].z = fmaf(inv, tmp[i].z, facc[i].z);
            facc[i].w = fmaf(inv, tmp[i].w, facc[i].w);
        }
    }

    // ---- rate 0: self key, prob = 1. score*log2e = |q'|^2 / QSCALE_.
    {
        float s = 0.f;
        #pragma unroll
        for (int i = 0; i < 8; i++) {
            s = fmaf(q4[i].x, q4[i].x, s); s = fmaf(q4[i].y, q4[i].y, s);
            s = fmaf(q4[i].z, q4[i].z, s); s = fmaf(q4[i].w, q4[i].w, s);
        }
        s += __shfl_xor_sync(0xffffffffu, s, 16);
        den += ex2(s * QINV_);
        #pragma unroll
        for (int i = 0; i < 8; i++) {     // out += q (unscaled) = q' / QSCALE_
            facc[i].x = fmaf(QINV_, q4[i].x, facc[i].x);
            facc[i].y = fmaf(QINV_, q4[i].y, facc[i].y);
            facc[i].z = fmaf(QINV_, q4[i].z, facc[i].z);
            facc[i].w = fmaf(QINV_, q4[i].w, facc[i].w);
        }
    }

    // ---- writes
    if (hf == 0)
        g_denoms[((size_t)b * L_ + t_glob) * H_ + h] = den;
    {
        float* op = out + (size_t)b * L_ * D_ + (size_t)t_glob * D_ + h * HD_ + 32 * hf;
        #pragma unroll
        for (int i = 0; i < 8; i++)
            *reinterpret_cast<float4*>(op + 4 * i) = facc[i];
    }

    // ---- last CTA per (b,chunk): head-softmax combine
    __threadfence();
    __shared__ unsigned int s_last;
    __syncthreads();
    if (tid == 0)
        s_last = (atomicInc(&g_cnt[b * (L_ / CHUNK_) + chunk], H_ - 1) == H_ - 1);
    __syncthreads();
    if (s_last) {
        const int k = lane;
        for (int t0 = w; t0 < CHUNK_; t0 += 16) {
            const size_t tok = (size_t)b * L_ + chunk * CHUNK_ + t0;
            const float v = __ldcg(&g_denoms[tok * H_ + k]);   // lane = head
            float mx = v;
            #pragma unroll
            for (int off = 16; off > 0; off >>= 1)
                mx = fmaxf(mx, __shfl_xor_sync(0xffffffffu, mx, off));
            const float e = __expf(v - mx);
            float sum = e;
            #pragma unroll
            for (int off = 16; off > 0; off >>= 1)
                sum += __shfl_xor_sync(0xffffffffu, sum, off);
            const float wgt = e / sum;
            float4* row = reinterpret_cast<float4*>(out + tok * D_);
            #pragma unroll
            for (int it = 0; it < 16; it++) {
                const int idx = k + 32 * it;
                const float ww = __shfl_sync(0xffffffffu, wgt, idx >> 4);
                float4 vv = __ldcg(&row[idx]);
                vv.x *= ww; vv.y *= ww; vv.z *= ww; vv.w *= ww;
                row[idx] = vv;
            }
        }
    }
}

extern "C" void kernel_launch(void* const* d_in, const int* in_sizes, int n_in,
                              void* d_out, int out_size) {
    const float* x = (const float*)d_in[0];
    float* out = (float*)d_out;

    const int smem_bytes = CHUNK_ * 16 * (int)sizeof(float4);   // 65536 B
    cudaFuncSetAttribute(dda_fused_kernel,
                         cudaFuncAttributeMaxDynamicSharedMemorySize, smem_bytes);

    dim3 grid(L_ / CHUNK_, H_, B_);
    dda_fused_kernel<<<grid, NT_, smem_bytes>>>(x, out);
}